// round 10
// baseline (speedup 1.0000x reference)
#include <cuda_runtime.h>

// AngularSymmetry B=16, M=64.
//  prep (132 blocks x 256): SD[b][m][k] = wgt*(g[(k+m)%64][k] + g[k][(k+m)%64]),
//    m=0..32; g = __expf(-4 d^2)*dc; wgt = 0.125 (m=0), 0.5 (m=32), 1 else.
//    Also zeroes the 6144-float output (atomics accumulate into it).
//  main (2048 blocks x 128, PDL-overlapped): block = (b, i, m-half h).
//    Thread (k = tid&63, g' = tid>>6): m = 16h + 2t + g' + 1, t = 0..7
//    (tiles m = 1..32 across h,g'); diagonal on h==0,g'==0 warps (SD row0 x4).
//    Replicated smem (128 entries) -> unmasked j, immediate-offset addressing.
//    Cody-Waite fast cos, packed f32x2 powers/accums; halves combined via
//    atomicAdd onto zeroed out (2 commutative adds -> deterministic).

#define B_DIM 16
#define M_DIM 64
#define SD_STRIDE (33 * 64)     // 2112 floats per batch
#define SD_TOTAL (B_DIM * SD_STRIDE)
#define OUT_TOTAL (B_DIM * M_DIM * 6)

__device__ float SD_buf[SD_TOTAL];

__global__ __launch_bounds__(256)
void prep_kernel(const float* __restrict__ d, const float* __restrict__ dc,
                 float* __restrict__ out)
{
    const int e = blockIdx.x * 256 + threadIdx.x;
    if (e < OUT_TOTAL) out[e] = 0.0f;
    if (e >= SD_TOTAL) return;
    const int b = e / SD_STRIDE;
    const int r = e - b * SD_STRIDE;
    const int m = r >> 6;
    const int k = r & 63;
    const int j = (k + m) & 63;

    const float* db  = d  + b * 4096;
    const float* dcb = dc + b * 4096;

    float djk = db[j * 64 + k];
    float dkj = db[k * 64 + j];
    float gjk = __expf(-4.0f * djk * djk) * dcb[j * 64 + k];
    float gkj = __expf(-4.0f * dkj * dkj) * dcb[k * 64 + j];

    const float w = (m == 0) ? 0.125f : ((m == 32) ? 0.5f : 1.0f);
    SD_buf[e] = w * (gjk + gkj);
}

// ---- packed f32x2 helpers ----
typedef unsigned long long u64;
__device__ __forceinline__ u64 pack2(float lo, float hi) {
    u64 r; asm("mov.b64 %0, {%1, %2};" : "=l"(r) : "f"(lo), "f"(hi)); return r;
}
__device__ __forceinline__ void unpack2(u64 v, float& lo, float& hi) {
    asm("mov.b64 {%0, %1}, %2;" : "=f"(lo), "=f"(hi) : "l"(v));
}
__device__ __forceinline__ u64 mul2(u64 a, u64 b) {
    u64 r; asm("mul.rn.f32x2 %0, %1, %2;" : "=l"(r) : "l"(a), "l"(b)); return r;
}
__device__ __forceinline__ u64 add2(u64 a, u64 b) {
    u64 r; asm("add.rn.f32x2 %0, %1, %2;" : "=l"(r) : "l"(a), "l"(b)); return r;
}
__device__ __forceinline__ u64 fma2(u64 a, u64 b, u64 c) {
    u64 r; asm("fma.rn.f32x2 %0, %1, %2, %3;" : "=l"(r) : "l"(a), "l"(b), "l"(c)); return r;
}

// Fast cos: exact RNE(x/2pi) via magic-number fma, 2-word Cody-Waite
// reduction, MUFU cos. Phase error ~1e-7 rad up to |x|~4e6.
__device__ __forceinline__ float fast_cos(float x) {
    const float MAGIC = 12582912.0f;                 // 1.5 * 2^23
    float q = fmaf(x, 0.15915494309189535f, MAGIC) - MAGIC;
    float r = fmaf(q, -6.28318548202514648f, x);     // C1 = fp32(2*pi)
    r = fmaf(q, 1.74845553146599e-7f, r);            // C2 correction
    return __cosf(r);
}

__global__ __launch_bounds__(128, 16)
void angular_main(const float* __restrict__ dc,
                  const float* __restrict__ d,
                  const float* __restrict__ coords,
                  float* __restrict__ out)
{
    const int blk = blockIdx.x;         // 0..2047
    const int b   = blk >> 7;
    const int rem = blk & 127;
    const int i   = rem >> 1;
    const int h   = rem & 1;            // m-half: 0 -> m 1..16 (+diag), 1 -> 17..32

    __shared__ float4 s_v4[2 * M_DIM];  // replicated: [j] == [j+64]
    __shared__ float  s_F[2 * M_DIM];   // replicated
    __shared__ u64    s_red[4][3];

    const int tid = threadIdx.x;        // 0..127

    // Prologue: only harness inputs (safe before prep completes under PDL).
    // All 128 threads build one replica entry each (tid = copy*64 + j).
    {
        const int j = tid & 63;
        const float* cb = coords + (size_t)b * 192;
        float cx = cb[i * 3 + 0];
        float cy = cb[i * 3 + 1];
        float cz = cb[i * 3 + 2];
        float4 v;
        v.x = cb[j * 3 + 0] - cx;
        v.y = cb[j * 3 + 1] - cy;
        v.z = cb[j * 3 + 2] - cz;
        v.w = d[(size_t)b * 4096 + i * 64 + j];
        float F = dc[(size_t)b * 4096 + i * 64 + j] * __expf(-4.0f * v.w * v.w);
        s_v4[tid] = v;
        s_F[tid]  = F;
    }
    __syncthreads();

    // PDL fence: prep's SD_buf writes (and out zeroing) visible past here.
    cudaGridDependencySynchronize();

    const int k  = tid & 63;
    const int gp = tid >> 6;            // 0..1

    const float4 vk = s_v4[k];
    const float  Fk = s_F[k];
    const int m0 = 16 * h + gp + 1;     // first m; step +2 per iteration
    // Immediate-offset bases: iteration t uses index base + 2t.
    const float4* vbase = s_v4 + (k + m0);               // j = k+m0+2t (max 95)
    const float*  fbase = s_F  + (k + m0);
    const float*  sbase = SD_buf + b * SD_STRIDE + (m0 << 6) + k;  // +128 floats/t

    const u64 ONE2 = 0x3F8000003F800000ull;  // (1.0f, 1.0f)
    u64 acc2 = 0, acc4 = 0, acc8 = 0;        // (lambda=+1, lambda=-1) per zeta

    // 8 pair iterations: m = m0 + 2t tiles m = 1..32 over (h, g').
    #pragma unroll
    for (int t = 0; t < 8; t++) {
        float  Sv = sbase[t << 7];           // LDG [base + 512B*t], coalesced
        float4 vj = vbase[t << 1];           // LDS.128 [base + 32B*t]
        float  Fj = fbase[t << 1];           // LDS.32  [base + 8B*t]

        float dot = vj.x * vk.x + vj.y * vk.y + vj.z * vk.z;
        float den = vj.w * vk.w + 1e-5f;
        float c   = fast_cos(dot / den);     // IEEE div kept for tail accuracy
        float w   = Fj * Sv;                 // Fk applied after the loop

        u64 cc  = pack2(c, __int_as_float(__float_as_int(c) ^ 0x80000000));
        u64 tpm = add2(cc, ONE2);            // (1+c, 1-c)
        u64 t2  = mul2(tpm, tpm);
        u64 t4  = mul2(t2, t2);
        u64 t8  = mul2(t4, t4);
        u64 wp  = pack2(w, w);

        acc2 = fma2(t2, wp, acc2);
        acc4 = fma2(t4, wp, acc4);
        acc8 = fma2(t8, wp, acc8);
    }

    // Diagonal (j == k): h==0, g'==0 warps only, weight x4 on SD row 0
    // (0.125 baked in; 4 * 0.125 * 2*g_kk * Fk^2 = exactly one ordered term).
    if (h == 0 && gp == 0) {
        float  Sv = 4.0f * SD_buf[b * SD_STRIDE + k];
        float dot = vk.x * vk.x + vk.y * vk.y + vk.z * vk.z;
        float den = vk.w * vk.w + 1e-5f;
        float c   = fast_cos(dot / den);
        float w   = Fk * Sv;                 // Fj == Fk on the diagonal

        u64 cc  = pack2(c, __int_as_float(__float_as_int(c) ^ 0x80000000));
        u64 tpm = add2(cc, ONE2);
        u64 t2  = mul2(tpm, tpm);
        u64 t4  = mul2(t2, t2);
        u64 t8  = mul2(t4, t4);
        u64 wp  = pack2(w, w);

        acc2 = fma2(t2, wp, acc2);
        acc4 = fma2(t4, wp, acc4);
        acc8 = fma2(t8, wp, acc8);
    }

    // Apply hoisted Fk (packed) before reduction (Fk varies by k)
    {
        u64 Fkp = pack2(Fk, Fk);
        acc2 = mul2(acc2, Fkp);
        acc4 = mul2(acc4, Fkp);
        acc8 = mul2(acc8, Fkp);
    }

    // Packed warp reduction (64-bit shuffles + add.rn.f32x2)
    #pragma unroll
    for (int off = 16; off > 0; off >>= 1) {
        acc2 = add2(acc2, __shfl_down_sync(0xffffffffu, acc2, off));
        acc4 = add2(acc4, __shfl_down_sync(0xffffffffu, acc4, off));
        acc8 = add2(acc8, __shfl_down_sync(0xffffffffu, acc8, off));
    }

    const int wid  = tid >> 5;   // 0..3
    const int lane = tid & 31;
    if (lane == 0) {
        s_red[wid][0] = acc2; s_red[wid][1] = acc4; s_red[wid][2] = acc8;
    }
    __syncthreads();

    if (tid < 3) {
        u64 s = add2(add2(s_red[0][tid], s_red[1][tid]),
                     add2(s_red[2][tid], s_red[3][tid]));
        float plus, minus;
        unpack2(s, plus, minus);
        // scale = 2^(1 - zeta), zeta = [2,4,8]
        const float scale = (tid == 0) ? 0.5f : ((tid == 1) ? 0.125f : 0.0078125f);
        float* o = out + ((size_t)b * 64 + i) * 6;
        atomicAdd(&o[tid],     plus  * scale);   // lambda = +1
        atomicAdd(&o[3 + tid], minus * scale);   // lambda = -1
    }
}

extern "C" void kernel_launch(void* const* d_in, const int* in_sizes, int n_in,
                              void* d_out, int out_size)
{
    const float* d_cutoff = (const float*)d_in[0];
    const float* d        = (const float*)d_in[1];
    const float* coords   = (const float*)d_in[2];
    float* out = (float*)d_out;

    prep_kernel<<<(SD_TOTAL + 255) / 256, 256>>>(d, d_cutoff, out);

    // Main launched with programmatic stream serialization (PDL): may start
    // while prep is still in flight; the grid-dependency sync inside the
    // kernel orders SD_buf reads / out atomics after prep completion.
    cudaLaunchConfig_t cfg = {};
    cfg.gridDim  = dim3(2048, 1, 1);
    cfg.blockDim = dim3(128, 1, 1);
    cfg.dynamicSmemBytes = 0;
    cfg.stream = 0;
    cudaLaunchAttribute attr[1];
    attr[0].id = cudaLaunchAttributeProgrammaticStreamSerialization;
    attr[0].val.programmaticStreamSerializationAllowed = 1;
    cfg.attrs = attr;
    cfg.numAttrs = 1;
    cudaLaunchKernelEx(&cfg, angular_main, d_cutoff, d, coords, out);
}

// round 11
// speedup vs baseline: 1.2384x; 1.2384x over previous
#include <cuda_runtime.h>

// AngularSymmetry B=16, M=64.
//  prep (132 blocks x 256): SD[b][m][k] = wgt*(g[(k+m)%64][k] + g[k][(k+m)%64]),
//    m=0..32; g = __expf(-4 d^2)*dc; wgt = 0.125 (m=0), 0.5 (m=32), 1 else.
//  main (1024 blocks x 256, PDL-overlapped): block=(b,i).
//    m = 4t+g+1 (t=0..7, group g=tid>>6); diagonal on g==0 (SD row0 x4).
//    Replicated smem -> immediate-offset addressing.
//    Division via rcp.approx + 2-fma Newton refinement (<=1 ulp, 4 instrs).
//    Cody-Waite fast cos, packed f32x2 powers/accumulators/reduction.

#define B_DIM 16
#define M_DIM 64
#define SD_STRIDE (33 * 64)     // 2112 floats per batch
#define SD_TOTAL (B_DIM * SD_STRIDE)

__device__ float SD_buf[SD_TOTAL];

__global__ __launch_bounds__(256)
void prep_kernel(const float* __restrict__ d, const float* __restrict__ dc)
{
    const int e = blockIdx.x * 256 + threadIdx.x;
    if (e >= SD_TOTAL) return;
    const int b = e / SD_STRIDE;
    const int r = e - b * SD_STRIDE;
    const int m = r >> 6;
    const int k = r & 63;
    const int j = (k + m) & 63;

    const float* db  = d  + b * 4096;
    const float* dcb = dc + b * 4096;

    float djk = db[j * 64 + k];
    float dkj = db[k * 64 + j];
    float gjk = __expf(-4.0f * djk * djk) * dcb[j * 64 + k];
    float gkj = __expf(-4.0f * dkj * dkj) * dcb[k * 64 + j];

    const float w = (m == 0) ? 0.125f : ((m == 32) ? 0.5f : 1.0f);
    SD_buf[e] = w * (gjk + gkj);
}

// ---- packed f32x2 helpers ----
typedef unsigned long long u64;
__device__ __forceinline__ u64 pack2(float lo, float hi) {
    u64 r; asm("mov.b64 %0, {%1, %2};" : "=l"(r) : "f"(lo), "f"(hi)); return r;
}
__device__ __forceinline__ void unpack2(u64 v, float& lo, float& hi) {
    asm("mov.b64 {%0, %1}, %2;" : "=f"(lo), "=f"(hi) : "l"(v));
}
__device__ __forceinline__ u64 mul2(u64 a, u64 b) {
    u64 r; asm("mul.rn.f32x2 %0, %1, %2;" : "=l"(r) : "l"(a), "l"(b)); return r;
}
__device__ __forceinline__ u64 add2(u64 a, u64 b) {
    u64 r; asm("add.rn.f32x2 %0, %1, %2;" : "=l"(r) : "l"(a), "l"(b)); return r;
}
__device__ __forceinline__ u64 fma2(u64 a, u64 b, u64 c) {
    u64 r; asm("fma.rn.f32x2 %0, %1, %2, %3;" : "=l"(r) : "l"(a), "l"(b), "l"(c)); return r;
}

// Newton-refined reciprocal divide: MUFU.RCP + 3 FMA, <= 1 ulp
// (equals RN(x/y) for the vast majority of inputs).
__device__ __forceinline__ float fast_div(float x, float y) {
    float r0;
    asm("rcp.approx.f32 %0, %1;" : "=f"(r0) : "f"(y));
    float q0 = x * r0;
    return fmaf(fmaf(-y, q0, x), r0, q0);
}

// Fast cos: exact RNE(x/2pi) via magic-number fma, 2-word Cody-Waite
// reduction, MUFU cos. Phase error ~1e-9*|x| — negligible up to |x|~1e6.
__device__ __forceinline__ float fast_cos(float x) {
    const float MAGIC = 12582912.0f;                 // 1.5 * 2^23
    float q = fmaf(x, 0.15915494309189535f, MAGIC) - MAGIC;
    float r = fmaf(q, -6.28318548202514648f, x);     // C1 = fp32(2*pi)
    r = fmaf(q, 1.74845553146599e-7f, r);            // C2 correction
    return __cosf(r);
}

__global__ __launch_bounds__(256, 7)
void angular_main(const float* __restrict__ dc,
                  const float* __restrict__ d,
                  const float* __restrict__ coords,
                  float* __restrict__ out)
{
    const int bi = blockIdx.x;      // 0..1023
    const int b  = bi >> 6;
    const int i  = bi & 63;

    __shared__ float4 s_v4[2 * M_DIM];      // replicated: [j] == [j+64]
    __shared__ float  s_F[2 * M_DIM];       // replicated
    __shared__ u64    s_red[8][3];

    const int tid = threadIdx.x;

    // Prologue: only harness inputs (safe before prep completes under PDL).
    if (tid < 128) {
        const int j = tid & 63;
        const float* cb = coords + (size_t)b * 192;
        float cx = cb[i * 3 + 0];
        float cy = cb[i * 3 + 1];
        float cz = cb[i * 3 + 2];
        float4 v;
        v.x = cb[j * 3 + 0] - cx;
        v.y = cb[j * 3 + 1] - cy;
        v.z = cb[j * 3 + 2] - cz;
        v.w = d[(size_t)b * 4096 + i * 64 + j];
        float F = dc[(size_t)b * 4096 + i * 64 + j] * __expf(-4.0f * v.w * v.w);
        s_v4[tid] = v;          // tid = copy*64 + j
        s_F[tid]  = F;
    }
    __syncthreads();

    // PDL fence: prep's SD_buf writes must be visible past this point.
    cudaGridDependencySynchronize();

    const int k = tid & 63;
    const int g = tid >> 6;    // 0..3

    const float4 vk = s_v4[k];
    const float  Fk = s_F[k];
    // Bases for immediate-offset addressing: iteration t uses index base + 4t.
    const float4* vbase = s_v4 + (k + g + 1);     // j = k+g+1+4t  (max 95 < 128)
    const float*  fbase = s_F  + (k + g + 1);
    const float*  sbase = SD_buf + b * SD_STRIDE + ((g + 1) << 6) + k;  // +256*t

    const u64 ONE2 = 0x3F8000003F800000ull;  // ( 1.0f,  1.0f)
    const u64 PM1  = 0xBF8000003F800000ull;  // ( 1.0f, -1.0f)  lo=+1, hi=-1
    u64 acc2 = 0, acc4 = 0, acc8 = 0;        // (lambda=+1, lambda=-1) per zeta

    // 8 pair iterations: m = 4t+g+1 covers m = 1..32 across the 4 groups.
    #pragma unroll
    for (int t = 0; t < 8; t++) {
        float  Sv = sbase[t << 8];           // LDG [base + 1024B*t], coalesced
        float4 vj = vbase[t << 2];           // LDS.128 [base + 64B*t]
        float  Fj = fbase[t << 2];           // LDS.32  [base + 16B*t]

        float dot = vj.x * vk.x + vj.y * vk.y + vj.z * vk.z;
        float den = vj.w * vk.w + 1e-5f;
        float c   = fast_cos(fast_div(dot, den));
        float w   = Fj * Sv;                 // Fk applied after the loop

        u64 tpm = fma2(pack2(c, c), PM1, ONE2);   // (1+c, 1-c)
        u64 t2  = mul2(tpm, tpm);
        u64 t4  = mul2(t2, t2);
        u64 t8  = mul2(t4, t4);
        u64 wp  = pack2(w, w);

        acc2 = fma2(t2, wp, acc2);
        acc4 = fma2(t4, wp, acc4);
        acc8 = fma2(t8, wp, acc8);
    }

    // Diagonal (j == k): g==0 warps only, weight x4 on SD row 0
    // (0.125 baked in; 0.5*(2 g_kk) = exactly one ordered term).
    if (g == 0) {
        float  Sv = 4.0f * SD_buf[b * SD_STRIDE + k];
        float dot = vk.x * vk.x + vk.y * vk.y + vk.z * vk.z;
        float den = vk.w * vk.w + 1e-5f;
        float c   = fast_cos(fast_div(dot, den));
        float w   = Fk * Sv;                 // Fj == Fk on the diagonal

        u64 tpm = fma2(pack2(c, c), PM1, ONE2);
        u64 t2  = mul2(tpm, tpm);
        u64 t4  = mul2(t2, t2);
        u64 t8  = mul2(t4, t4);
        u64 wp  = pack2(w, w);

        acc2 = fma2(t2, wp, acc2);
        acc4 = fma2(t4, wp, acc4);
        acc8 = fma2(t8, wp, acc8);
    }

    // Apply hoisted Fk (packed) before reduction (Fk varies by k)
    {
        u64 Fkp = pack2(Fk, Fk);
        acc2 = mul2(acc2, Fkp);
        acc4 = mul2(acc4, Fkp);
        acc8 = mul2(acc8, Fkp);
    }

    // Packed warp reduction (64-bit shuffles + add.rn.f32x2)
    #pragma unroll
    for (int off = 16; off > 0; off >>= 1) {
        acc2 = add2(acc2, __shfl_down_sync(0xffffffffu, acc2, off));
        acc4 = add2(acc4, __shfl_down_sync(0xffffffffu, acc4, off));
        acc8 = add2(acc8, __shfl_down_sync(0xffffffffu, acc8, off));
    }

    const int wid  = tid >> 5;
    const int lane = tid & 31;
    if (lane == 0) {
        s_red[wid][0] = acc2; s_red[wid][1] = acc4; s_red[wid][2] = acc8;
    }
    __syncthreads();

    if (tid < 3) {
        u64 s = s_red[0][tid];
        #pragma unroll
        for (int w = 1; w < 8; w++) s = add2(s, s_red[w][tid]);
        float plus, minus;
        unpack2(s, plus, minus);
        // scale = 2^(1 - zeta), zeta = [2,4,8]
        const float scale = (tid == 0) ? 0.5f : ((tid == 1) ? 0.125f : 0.0078125f);
        float* o = out + (size_t)bi * 6;
        o[tid]     = plus  * scale;   // lambda = +1
        o[3 + tid] = minus * scale;   // lambda = -1
    }
}

extern "C" void kernel_launch(void* const* d_in, const int* in_sizes, int n_in,
                              void* d_out, int out_size)
{
    const float* d_cutoff = (const float*)d_in[0];
    const float* d        = (const float*)d_in[1];
    const float* coords   = (const float*)d_in[2];
    float* out = (float*)d_out;

    prep_kernel<<<(SD_TOTAL + 255) / 256, 256>>>(d, d_cutoff);

    // Main launched with programmatic stream serialization (PDL): may start
    // while prep is still in flight; the grid-dependency sync inside the
    // kernel orders SD_buf reads after prep completion.
    cudaLaunchConfig_t cfg = {};
    cfg.gridDim  = dim3(1024, 1, 1);
    cfg.blockDim = dim3(256, 1, 1);
    cfg.dynamicSmemBytes = 0;
    cfg.stream = 0;
    cudaLaunchAttribute attr[1];
    attr[0].id = cudaLaunchAttributeProgrammaticStreamSerialization;
    attr[0].val.programmaticStreamSerializationAllowed = 1;
    cfg.attrs = attr;
    cfg.numAttrs = 1;
    cudaLaunchKernelEx(&cfg, angular_main, d_cutoff, d, coords, out);
}

// round 12
// speedup vs baseline: 1.2679x; 1.0238x over previous
#include <cuda_runtime.h>

// AngularSymmetry B=16, M=64.
//  prep (132 blocks x 256): SD[b][m][k] = wgt*(g[(k+m)%64][k] + g[k][(k+m)%64]),
//    m=0..32; g = __expf(-4 d^2)*dc; wgt = 0.125 (m=0), 0.5 (m=32), 1 else.
//  main (1024 blocks x 256, PDL-overlapped): block=(b,i).
//    m = 4t+g+1 (t=0..7, group g=tid>>6); diagonal on g==0 (SD row0 x4),
//    issued FIRST so its MUFU chain overlaps loop warm-up.
//    Sv LDGs prefetched in batches of 4 (MLP). Replicated smem ->
//    immediate-offset addressing. Division via raw rcp.approx (quotient
//    <=1ulp; large-theta terms measured insensitive R10->R11).
//    Cody-Waite fast cos, packed f32x2 powers/accumulators/reduction.

#define B_DIM 16
#define M_DIM 64
#define SD_STRIDE (33 * 64)     // 2112 floats per batch
#define SD_TOTAL (B_DIM * SD_STRIDE)

__device__ float SD_buf[SD_TOTAL];

__global__ __launch_bounds__(256)
void prep_kernel(const float* __restrict__ d, const float* __restrict__ dc)
{
    const int e = blockIdx.x * 256 + threadIdx.x;
    if (e >= SD_TOTAL) return;
    const int b = e / SD_STRIDE;
    const int r = e - b * SD_STRIDE;
    const int m = r >> 6;
    const int k = r & 63;
    const int j = (k + m) & 63;

    const float* db  = d  + b * 4096;
    const float* dcb = dc + b * 4096;

    float djk = db[j * 64 + k];
    float dkj = db[k * 64 + j];
    float gjk = __expf(-4.0f * djk * djk) * dcb[j * 64 + k];
    float gkj = __expf(-4.0f * dkj * dkj) * dcb[k * 64 + j];

    const float w = (m == 0) ? 0.125f : ((m == 32) ? 0.5f : 1.0f);
    SD_buf[e] = w * (gjk + gkj);
}

// ---- packed f32x2 helpers ----
typedef unsigned long long u64;
__device__ __forceinline__ u64 pack2(float lo, float hi) {
    u64 r; asm("mov.b64 %0, {%1, %2};" : "=l"(r) : "f"(lo), "f"(hi)); return r;
}
__device__ __forceinline__ void unpack2(u64 v, float& lo, float& hi) {
    asm("mov.b64 {%0, %1}, %2;" : "=f"(lo), "=f"(hi) : "l"(v));
}
__device__ __forceinline__ u64 mul2(u64 a, u64 b) {
    u64 r; asm("mul.rn.f32x2 %0, %1, %2;" : "=l"(r) : "l"(a), "l"(b)); return r;
}
__device__ __forceinline__ u64 add2(u64 a, u64 b) {
    u64 r; asm("add.rn.f32x2 %0, %1, %2;" : "=l"(r) : "l"(a), "l"(b)); return r;
}
__device__ __forceinline__ u64 fma2(u64 a, u64 b, u64 c) {
    u64 r; asm("fma.rn.f32x2 %0, %1, %2, %3;" : "=l"(r) : "l"(a), "l"(b), "l"(c)); return r;
}

// Raw reciprocal divide: MUFU.RCP + FMUL. Quotient error ~1 ulp; the only
// terms sensitive to this (huge theta from tiny denominators) are measured
// insensitive in the output metric (R10->R11 rel_err unchanged at 1-ulp).
__device__ __forceinline__ float fast_div(float x, float y) {
    float r0;
    asm("rcp.approx.f32 %0, %1;" : "=f"(r0) : "f"(y));
    return x * r0;
}

// Fast cos: exact RNE(x/2pi) via magic-number fma, 2-word Cody-Waite
// reduction, MUFU cos. Phase error ~1e-10*|x| — load-bearing for |x|~1e5.
__device__ __forceinline__ float fast_cos(float x) {
    const float MAGIC = 12582912.0f;                 // 1.5 * 2^23
    float q = fmaf(x, 0.15915494309189535f, MAGIC) - MAGIC;
    float r = fmaf(q, -6.28318548202514648f, x);     // C1 = fp32(2*pi)
    r = fmaf(q, 1.74845553146599e-7f, r);            // C2 correction
    return __cosf(r);
}

__global__ __launch_bounds__(256, 7)
void angular_main(const float* __restrict__ dc,
                  const float* __restrict__ d,
                  const float* __restrict__ coords,
                  float* __restrict__ out)
{
    const int bi = blockIdx.x;      // 0..1023
    const int b  = bi >> 6;
    const int i  = bi & 63;

    __shared__ float4 s_v4[2 * M_DIM];      // replicated: [j] == [j+64]
    __shared__ float  s_F[2 * M_DIM];       // replicated
    __shared__ u64    s_red[8][3];

    const int tid = threadIdx.x;

    // Prologue: only harness inputs (safe before prep completes under PDL).
    if (tid < 128) {
        const int j = tid & 63;
        const float* cb = coords + (size_t)b * 192;
        float cx = cb[i * 3 + 0];
        float cy = cb[i * 3 + 1];
        float cz = cb[i * 3 + 2];
        float4 v;
        v.x = cb[j * 3 + 0] - cx;
        v.y = cb[j * 3 + 1] - cy;
        v.z = cb[j * 3 + 2] - cz;
        v.w = d[(size_t)b * 4096 + i * 64 + j];
        float F = dc[(size_t)b * 4096 + i * 64 + j] * __expf(-4.0f * v.w * v.w);
        s_v4[tid] = v;          // tid = copy*64 + j
        s_F[tid]  = F;
    }
    __syncthreads();

    // PDL fence: prep's SD_buf writes must be visible past this point.
    cudaGridDependencySynchronize();

    const int k = tid & 63;
    const int g = tid >> 6;    // 0..3

    const float4 vk = s_v4[k];
    const float  Fk = s_F[k];
    // Bases for immediate-offset addressing: iteration t uses index base + 4t.
    const float4* vbase = s_v4 + (k + g + 1);     // j = k+g+1+4t  (max 95 < 128)
    const float*  fbase = s_F  + (k + g + 1);
    const float*  sbase = SD_buf + b * SD_STRIDE + ((g + 1) << 6) + k;  // +256*t

    const u64 ONE2 = 0x3F8000003F800000ull;  // ( 1.0f,  1.0f)
    const u64 PM1  = 0xBF8000003F800000ull;  // ( 1.0f, -1.0f)  lo=+1, hi=-1
    u64 acc2 = 0, acc4 = 0, acc8 = 0;        // (lambda=+1, lambda=-1) per zeta

    // Diagonal (j == k) FIRST: g==0 warps only, weight x4 on SD row 0
    // (0.125 baked in; 0.5*(2 g_kk) = exactly one ordered term). Its MUFU
    // chain overlaps the pair-loop warm-up.
    if (g == 0) {
        float  Sv = 4.0f * SD_buf[b * SD_STRIDE + k];
        float dot = vk.x * vk.x + vk.y * vk.y + vk.z * vk.z;
        float den = vk.w * vk.w + 1e-5f;
        float c   = fast_cos(fast_div(dot, den));
        float w   = Fk * Sv;                 // Fj == Fk on the diagonal

        u64 tpm = fma2(pack2(c, c), PM1, ONE2);
        u64 t2  = mul2(tpm, tpm);
        u64 t4  = mul2(t2, t2);
        u64 t8  = mul2(t4, t4);
        u64 wp  = pack2(w, w);

        acc2 = fma2(t2, wp, acc2);
        acc4 = fma2(t4, wp, acc4);
        acc8 = fma2(t8, wp, acc8);
    }

    // 8 pair iterations, m = 4t+g+1 (m = 1..32 across groups), in two
    // half-batches with Sv prefetched (MLP-4 LDG).
    #pragma unroll
    for (int half = 0; half < 2; half++) {
        float Svp[4];
        #pragma unroll
        for (int u = 0; u < 4; u++)
            Svp[u] = sbase[(half * 4 + u) << 8];   // LDG [base + 1024B*t]

        #pragma unroll
        for (int u = 0; u < 4; u++) {
            const int t = half * 4 + u;
            float4 vj = vbase[t << 2];             // LDS.128 [base + 64B*t]
            float  Fj = fbase[t << 2];             // LDS.32  [base + 16B*t]

            float dot = vj.x * vk.x + vj.y * vk.y + vj.z * vk.z;
            float den = vj.w * vk.w + 1e-5f;
            float c   = fast_cos(fast_div(dot, den));
            float w   = Fj * Svp[u];               // Fk applied after the loop

            u64 tpm = fma2(pack2(c, c), PM1, ONE2);   // (1+c, 1-c)
            u64 t2  = mul2(tpm, tpm);
            u64 t4  = mul2(t2, t2);
            u64 t8  = mul2(t4, t4);
            u64 wp  = pack2(w, w);

            acc2 = fma2(t2, wp, acc2);
            acc4 = fma2(t4, wp, acc4);
            acc8 = fma2(t8, wp, acc8);
        }
    }

    // Apply hoisted Fk (packed) before reduction (Fk varies by k)
    {
        u64 Fkp = pack2(Fk, Fk);
        acc2 = mul2(acc2, Fkp);
        acc4 = mul2(acc4, Fkp);
        acc8 = mul2(acc8, Fkp);
    }

    // Packed warp reduction (64-bit shuffles + add.rn.f32x2)
    #pragma unroll
    for (int off = 16; off > 0; off >>= 1) {
        acc2 = add2(acc2, __shfl_down_sync(0xffffffffu, acc2, off));
        acc4 = add2(acc4, __shfl_down_sync(0xffffffffu, acc4, off));
        acc8 = add2(acc8, __shfl_down_sync(0xffffffffu, acc8, off));
    }

    const int wid  = tid >> 5;
    const int lane = tid & 31;
    if (lane == 0) {
        s_red[wid][0] = acc2; s_red[wid][1] = acc4; s_red[wid][2] = acc8;
    }
    __syncthreads();

    if (tid < 3) {
        u64 s = s_red[0][tid];
        #pragma unroll
        for (int w = 1; w < 8; w++) s = add2(s, s_red[w][tid]);
        float plus, minus;
        unpack2(s, plus, minus);
        // scale = 2^(1 - zeta), zeta = [2,4,8]
        const float scale = (tid == 0) ? 0.5f : ((tid == 1) ? 0.125f : 0.0078125f);
        float* o = out + (size_t)bi * 6;
        o[tid]     = plus  * scale;   // lambda = +1
        o[3 + tid] = minus * scale;   // lambda = -1
    }
}

extern "C" void kernel_launch(void* const* d_in, const int* in_sizes, int n_in,
                              void* d_out, int out_size)
{
    const float* d_cutoff = (const float*)d_in[0];
    const float* d        = (const float*)d_in[1];
    const float* coords   = (const float*)d_in[2];
    float* out = (float*)d_out;

    prep_kernel<<<(SD_TOTAL + 255) / 256, 256>>>(d, d_cutoff);

    // Main launched with programmatic stream serialization (PDL): may start
    // while prep is still in flight; the grid-dependency sync inside the
    // kernel orders SD_buf reads after prep completion.
    cudaLaunchConfig_t cfg = {};
    cfg.gridDim  = dim3(1024, 1, 1);
    cfg.blockDim = dim3(256, 1, 1);
    cfg.dynamicSmemBytes = 0;
    cfg.stream = 0;
    cudaLaunchAttribute attr[1];
    attr[0].id = cudaLaunchAttributeProgrammaticStreamSerialization;
    attr[0].val.programmaticStreamSerializationAllowed = 1;
    cfg.attrs = attr;
    cfg.numAttrs = 1;
    cudaLaunchKernelEx(&cfg, angular_main, d_cutoff, d, coords, out);
}